// round 13
// baseline (speedup 1.0000x reference)
#include <cuda_runtime.h>
#include <cuda_fp16.h>
#include <cuda_pipeline.h>
#include <cstdint>

#define NN   100000
#define NE   1600000
#define DD   128
#define NG   64
#define NCLS 16
#define SBS  512
#define SNB  ((NN + SBS - 1) / SBS)   // 196

// ---------------- device scratch (no allocs; zero-init on load) ----------------
__device__ __align__(16) __half d_hb[NN * DD];      // h in fp16
__device__ __align__(16) __half d_neighb[NN * DD];  // aggregated (fp16)
__device__ __align__(16) __half d_x1b[NN * DD];
__device__ __align__(16) __half d_wimg[2][128 * 256]; // [layer][n][k0..255]
__device__ float d_gsum[NG * DD];
__device__ int d_deg[NN];
__device__ int d_off[NN];
__device__ int d_cursor[NN];
__device__ int d_sorted[NE];
__device__ int d_gcnt[NG];
__device__ int d_total;
__device__ int d_barrier;

// ---------------- PTX helpers ----------------
__device__ __forceinline__ uint32_t smem_to_u32(const void* p) {
    uint32_t a;
    asm("{ .reg .u64 t; cvta.to.shared.u64 t, %1; cvt.u32.u64 %0, t; }" : "=r"(a) : "l"(p));
    return a;
}
__device__ __forceinline__ void ldsm4(uint32_t* r, uint32_t addr) {
    asm volatile("ldmatrix.sync.aligned.m8n8.x4.shared.b16 {%0,%1,%2,%3}, [%4];"
                 : "=r"(r[0]), "=r"(r[1]), "=r"(r[2]), "=r"(r[3]) : "r"(addr));
}
__device__ __forceinline__ void mma_f16(float* c, const uint32_t* a, const uint32_t* b) {
    asm volatile(
        "mma.sync.aligned.m16n8k16.row.col.f32.f16.f16.f32 "
        "{%0,%1,%2,%3},{%4,%5,%6,%7},{%8,%9},{%0,%1,%2,%3};"
        : "+f"(c[0]), "+f"(c[1]), "+f"(c[2]), "+f"(c[3])
        : "r"(a[0]), "r"(a[1]), "r"(a[2]), "r"(a[3]), "r"(b[0]), "r"(b[1]));
}

// ---- #1: h fp32->fp16 + degree/graph counting + weight images ----
__global__ void k_cvth_count(const float4* __restrict__ in, uint4* __restrict__ out,
                             const int* __restrict__ dst, const int* __restrict__ gid,
                             const float* __restrict__ W1s, const float* __restrict__ W1n,
                             const float* __restrict__ W2s, const float* __restrict__ W2n) {
    int i = blockIdx.x * blockDim.x + threadIdx.x;   // covers 1.6M
    if (i < NE) atomicAdd(&d_deg[dst[i]], 1);
    if (i < NN) atomicAdd(&d_gcnt[gid[i]], 1);
    if (i < 2 * 128 * 128) {                          // weight images (both layers)
        int layer = i >> 14;
        int j = i & 16383;
        int k = j >> 7, n = j & 127;
        const float* Ws = layer ? W2s : W1s;
        const float* Wn = layer ? W2n : W1n;
        d_wimg[layer][n * 256 + k]       = __float2half_rn(Ws[k * 128 + n]);
        d_wimg[layer][n * 256 + 128 + k] = __float2half_rn(Wn[k * 128 + n]);
    }
    if (i >= NN * DD / 8) return;
    float4 a = in[2 * i], b = in[2 * i + 1];
    __half2 p0 = __floats2half2_rn(a.x, a.y);
    __half2 p1 = __floats2half2_rn(a.z, a.w);
    __half2 p2 = __floats2half2_rn(b.x, b.y);
    __half2 p3 = __floats2half2_rn(b.z, b.w);
    uint4 o;
    o.x = *(uint32_t*)&p0; o.y = *(uint32_t*)&p1;
    o.z = *(uint32_t*)&p2; o.w = *(uint32_t*)&p3;
    out[i] = o;
}

// ---- #2: fused scan (atomic ticket) + grid barrier + scatter ----
__global__ void k_scan_scatter(const int* __restrict__ src, const int* __restrict__ dst) {
    __shared__ int wsum[16];
    __shared__ int sbase;
    int t = threadIdx.x, lane = t & 31, w = t >> 5;
    int i = blockIdx.x * SBS + t;
    int v = (i < NN) ? d_deg[i] : 0;
    int x = v;
#pragma unroll
    for (int s = 1; s < 32; s <<= 1) {
        int y = __shfl_up_sync(0xFFFFFFFFu, x, s);
        if (lane >= s) x += y;
    }
    if (lane == 31) wsum[w] = x;
    __syncthreads();
    if (w == 0) {
        int ws = (lane < 16) ? wsum[lane] : 0;
#pragma unroll
        for (int s = 1; s < 16; s <<= 1) {
            int y = __shfl_up_sync(0xFFFFFFFFu, ws, s);
            if (lane >= s) ws += y;
        }
        if (lane < 16) wsum[lane] = ws;
    }
    __syncthreads();
    int incl = x + ((w > 0) ? wsum[w - 1] : 0);
    if (t == SBS - 1) sbase = atomicAdd(&d_total, incl);
    __syncthreads();
    if (i < NN) {
        int off = sbase + incl - v;
        d_off[i] = off;
        d_cursor[i] = off;
    }

    // ---- software grid barrier (all 196 blocks are co-resident) ----
    __threadfence();
    __syncthreads();
    if (t == 0) {
        atomicAdd(&d_barrier, 1);
        while (atomicAdd(&d_barrier, 0) < gridDim.x) { }
    }
    __syncthreads();

    // ---- scatter phase: grid-stride over edges ----
    int nthreads = gridDim.x * SBS;
    for (int e = blockIdx.x * SBS + t; e < NE; e += nthreads) {
        int p = atomicAdd(&d_cursor[dst[e]], 1);
        d_sorted[p] = src[e];
    }
}

// ---- #3 / #5: aggregation (2 edges/iter, fp16 accumulate) ----
__global__ void k_agg(const uint4* __restrict__ feat) {
    int warp = (blockIdx.x * blockDim.x + threadIdx.x) >> 5;
    int lane = threadIdx.x & 31;
    if (warp >= NN) return;
    const int half = lane >> 4;      // which edge of the pair
    const int sub = lane & 15;       // uint4 index within 256B row
    int e0 = d_off[warp];
    int deg = d_deg[warp];
    int e1 = e0 + deg;

    __half2 a0 = __float2half2_rn(0.f), a1 = a0, a2 = a0, a3 = a0;
    int e = e0;
#pragma unroll 4
    for (; e + 1 < e1; e += 2) {
        int s = __ldg(&d_sorted[e + half]);
        uint4 v = __ldg(&feat[s * 16 + sub]);
        a0 = __hadd2(a0, *(__half2*)&v.x);
        a1 = __hadd2(a1, *(__half2*)&v.y);
        a2 = __hadd2(a2, *(__half2*)&v.z);
        a3 = __hadd2(a3, *(__half2*)&v.w);
    }
    if (e < e1 && half == 0) {       // odd remainder: lanes 0-15 only
        int s = __ldg(&d_sorted[e]);
        uint4 v = __ldg(&feat[s * 16 + sub]);
        a0 = __hadd2(a0, *(__half2*)&v.x);
        a1 = __hadd2(a1, *(__half2*)&v.y);
        a2 = __hadd2(a2, *(__half2*)&v.z);
        a3 = __hadd2(a3, *(__half2*)&v.w);
    }

    // merge the two halves in fp32, scale by 1/deg, pack, write by lanes 0-15
    float2 f0 = __half22float2(a0), f1 = __half22float2(a1);
    float2 f2 = __half22float2(a2), f3 = __half22float2(a3);
    float fs[8] = { f0.x, f0.y, f1.x, f1.y, f2.x, f2.y, f3.x, f3.y };
    float inv = 1.0f / fmaxf((float)deg, 1.0f);
#pragma unroll
    for (int j = 0; j < 8; j++) {
        fs[j] += __shfl_xor_sync(0xFFFFFFFFu, fs[j], 16);
        fs[j] *= inv;
    }
    if (half == 0) {
        __half2 q0 = __floats2half2_rn(fs[0], fs[1]);
        __half2 q1 = __floats2half2_rn(fs[2], fs[3]);
        __half2 q2 = __floats2half2_rn(fs[4], fs[5]);
        __half2 q3 = __floats2half2_rn(fs[6], fs[7]);
        uint4 o;
        o.x = *(uint32_t*)&q0; o.y = *(uint32_t*)&q1;
        o.z = *(uint32_t*)&q2; o.w = *(uint32_t*)&q3;
        ((uint4*)d_neighb)[warp * 16 + sub] = o;
    }
}

// ---- #4 / #6: fused dual GEMM — 128m x 64n tiles, 2 CTAs/SM, cp.async ----
// D[128m,64n] = [As|An](128x256) @ Bimg_half(64n x 256k)^T
#define ROWB 528                          // padded row stride in bytes (264 halves)
#define SMA  (128 * ROWB)                 // 67584 (A tile)
#define SMB  (64 * ROWB)                  // 33792 (B half tile)
#define SM_TOT (SMA + SMB)                // 101376 -> 2 CTAs/SM

__global__ void __launch_bounds__(256, 2) k_gemm_mma(
    const uint4* __restrict__ Aself, const uint4* __restrict__ Aneigh,
    const uint4* __restrict__ Bimg, const float* __restrict__ bias,
    uint32_t* __restrict__ outp, const int* __restrict__ gid, int mode)
    // mode 0: relu + store fp16; mode 1: no relu, pool into d_gsum (no store)
{
    extern __shared__ __align__(16) char smem[];
    char* sA = smem;
    char* sB = smem + SMA;
    const int tid = threadIdx.x;
    const int wid = tid >> 5;
    const int lane = tid & 31;
    const int m_base = (blockIdx.x >> 1) * 128;
    const int n_base = (blockIdx.x & 1) * 64;

    // stage A via cp.async: rows = nodes, cols 0-127 self / 128-255 neigh
#pragma unroll
    for (int it = 0; it < 16; it++) {
        int idx = it * 256 + tid;           // 0..4095
        int row = idx >> 5, q = idx & 31;
        int m = m_base + row;
        const uint4* src = (q < 16) ? &Aself[m * 16 + q] : &Aneigh[m * 16 + (q - 16)];
        __pipeline_memcpy_async(sA + row * ROWB + q * 16, src, 16,
                                (m < NN) ? 0 : 16);
    }
    // stage B half via cp.async: rows n_base..n_base+63, [n][k] fp16
#pragma unroll
    for (int it = 0; it < 8; it++) {
        int idx = it * 256 + tid;           // 0..2047
        int row = idx >> 5, q = idx & 31;
        __pipeline_memcpy_async(sB + row * ROWB + q * 16,
                                &Bimg[(n_base + row) * 32 + q], 16, 0);
    }
    __pipeline_commit();
    __pipeline_wait_prior(0);
    __syncthreads();

    const int warpM = wid >> 1;   // 0..3 -> 32-row band
    const int warpN = wid & 1;    // 0..1 -> 32-col band

    float acc[2][4][4];
#pragma unroll
    for (int i = 0; i < 2; i++)
#pragma unroll
        for (int j = 0; j < 4; j++)
#pragma unroll
            for (int p = 0; p < 4; p++) acc[i][j][p] = 0.f;

    uint32_t aBase = smem_to_u32(sA) + (warpM * 32 + (lane & 15)) * ROWB + (lane >> 4) * 16;
    uint32_t bBase = smem_to_u32(sB) +
                     (warpN * 32 + (lane & 7) + ((lane >> 4) & 1) * 8) * ROWB +
                     ((lane >> 3) & 1) * 16;

#pragma unroll
    for (int ks = 0; ks < 16; ks++) {
        uint32_t a[2][4];
        ldsm4(a[0], aBase + ks * 32);
        ldsm4(a[1], aBase + 16 * ROWB + ks * 32);
        uint32_t b[2][4];
#pragma unroll
        for (int nb = 0; nb < 2; nb++)
            ldsm4(b[nb], bBase + nb * 16 * ROWB + ks * 32);
#pragma unroll
        for (int mi = 0; mi < 2; mi++)
#pragma unroll
            for (int nb = 0; nb < 2; nb++) {
                mma_f16(acc[mi][2 * nb],     a[mi], &b[nb][0]);
                mma_f16(acc[mi][2 * nb + 1], a[mi], &b[nb][2]);
            }
    }

    const int qcol = 2 * (lane & 3);
    const int qrow = lane >> 2;

    if (mode == 0) {
        // epilogue: bias + relu, fp16 pairs to global
#pragma unroll
        for (int ni = 0; ni < 4; ni++) {
            int n = n_base + warpN * 32 + ni * 8 + qcol;
            float b0 = bias[n], b1 = bias[n + 1];
#pragma unroll
            for (int mi = 0; mi < 2; mi++) {
                int m0 = m_base + warpM * 32 + mi * 16 + qrow;
#pragma unroll
                for (int half = 0; half < 2; half++) {
                    int m = m0 + half * 8;
                    if (m >= NN) continue;
                    float f0 = fmaxf(acc[mi][ni][2 * half]     + b0, 0.f);
                    float f1 = fmaxf(acc[mi][ni][2 * half + 1] + b1, 0.f);
                    __half2 pk = __floats2half2_rn(f0, f1);
                    outp[m * 64 + n / 2] = *(uint32_t*)&pk;
                }
            }
        }
    } else {
        // epilogue: bias (no relu), per-graph segmented pooling into d_gsum
        __syncthreads();                      // all ldsm reads of sA done
        float* scr = (float*)sA;              // 128 x 65 fp32 (padded) = 33280 B
        int* sg = (int*)(smem + 34816);       // gids (within sA region)
        if (tid < 128) {
            int m = m_base + tid;
            sg[tid] = (m < NN) ? gid[m] : -1;
        }
#pragma unroll
        for (int ni = 0; ni < 4; ni++) {
            int nl = warpN * 32 + ni * 8 + qcol;
            int n = n_base + nl;
            float b0 = bias[n], b1 = bias[n + 1];
#pragma unroll
            for (int mi = 0; mi < 2; mi++) {
                int ml0 = warpM * 32 + mi * 16 + qrow;
#pragma unroll
                for (int half = 0; half < 2; half++) {
                    int ml = ml0 + half * 8;
                    scr[ml * 65 + nl]     = acc[mi][ni][2 * half]     + b0;
                    scr[ml * 65 + nl + 1] = acc[mi][ni][2 * half + 1] + b1;
                }
            }
        }
        __syncthreads();
        if (tid < 64) {
            float pacc = 0.f;
            int cur = sg[0];
            for (int r = 0; r < 128; r++) {
                int m = m_base + r;
                if (m >= NN) break;
                int g = sg[r];
                if (g != cur) {
                    atomicAdd(&d_gsum[cur * DD + n_base + tid], pacc);
                    pacc = 0.f;
                    cur = g;
                }
                pacc += scr[r * 65 + tid];
            }
            if (cur >= 0) atomicAdd(&d_gsum[cur * DD + n_base + tid], pacc);
        }
    }
}

// ---- #7: classifier + cleanup ----
__global__ void k_cls_cleanup(const float* __restrict__ Wc, const float* __restrict__ bc,
                              float* __restrict__ out) {
    __shared__ float sm[DD];
    int b = blockIdx.x;
    int t = threadIdx.x;   // 256 threads
    if (b < NG) {
        if (t < DD) {
            float cnt = fmaxf((float)d_gcnt[b], 1.0f);
            sm[t] = d_gsum[b * DD + t] / cnt;
        }
        __syncthreads();
        if (t < NCLS) {
            float o = bc[t];
#pragma unroll 4
            for (int k = 0; k < DD; k++) o += sm[k] * Wc[k * NCLS + t];
            out[b * NCLS + t] = o;
        }
        if (t < DD) d_gsum[b * DD + t] = 0.f;
        if (t == 0) d_gcnt[b] = 0;
    }
    int i = b * 256 + t;
    if (i < NN) d_deg[i] = 0;
    if (i == 0) { d_total = 0; d_barrier = 0; }
}

// ---------------- launch ----------------
extern "C" void kernel_launch(void* const* d_in, const int* in_sizes, int n_in,
                              void* d_out, int out_size)
{
    const float* h   = (const float*)d_in[0];
    const int*   src = (const int*)d_in[1];
    const int*   dst = (const int*)d_in[2];
    const int*   gid = (const int*)d_in[3];
    int wb = (in_sizes[4] == 1) ? 5 : 4;
    const float* W1s = (const float*)d_in[wb + 0];
    const float* W1n = (const float*)d_in[wb + 1];
    const float* b1  = (const float*)d_in[wb + 2];
    const float* W2s = (const float*)d_in[wb + 3];
    const float* W2n = (const float*)d_in[wb + 4];
    const float* b2  = (const float*)d_in[wb + 5];
    const float* Wc  = (const float*)d_in[wb + 6];
    const float* bc  = (const float*)d_in[wb + 7];
    float* out = (float*)d_out;

    void *phb, *pnb, *px1, *pw;
    cudaGetSymbolAddress(&phb, d_hb);
    cudaGetSymbolAddress(&pnb, d_neighb);
    cudaGetSymbolAddress(&px1, d_x1b);
    cudaGetSymbolAddress(&pw, d_wimg);
    __half* hb = (__half*)phb;
    __half* nb = (__half*)pnb;
    __half* x1 = (__half*)px1;
    const uint4* wimg = (const uint4*)pw;

    cudaFuncSetAttribute(k_gemm_mma, cudaFuncAttributeMaxDynamicSharedMemorySize, SM_TOT);

    const int GB = 2 * ((NN + 127) / 128);   // 1564 CTAs (128m x 64n tiles)
    const uint4* B1 = wimg;                  // each image = 4096 uint4
    const uint4* B2 = wimg + 4096;

    // #1: h conversion + counting + weight images
    k_cvth_count<<<(NN * DD / 8 + 255) / 256, 256>>>((const float4*)h, (uint4*)hb,
                                                     dst, gid, W1s, W1n, W2s, W2n);
    // #2: fused scan + grid-barrier + scatter
    k_scan_scatter<<<SNB, SBS>>>(src, dst);
    // #3: layer-1 aggregation
    k_agg<<<NN / 8, 256>>>((const uint4*)hb);
    // #4: layer-1 GEMM  <-- ncu capture slot
    k_gemm_mma<<<GB, 256, SM_TOT>>>((const uint4*)hb, (const uint4*)nb, B1, b1,
                                    (uint32_t*)x1, gid, 0);
    // #5: layer-2 aggregation
    k_agg<<<NN / 8, 256>>>((const uint4*)x1);
    // #6: layer-2 GEMM + fused graph pooling into d_gsum
    k_gemm_mma<<<GB, 256, SM_TOT>>>((const uint4*)x1, (const uint4*)nb, B2, b2,
                                    (uint32_t*)x1, gid, 1);
    // #7: classifier + zero-invariant restore
    k_cls_cleanup<<<(NN + 255) / 256, 256>>>(Wc, bc, out);
}

// round 14
// speedup vs baseline: 1.0617x; 1.0617x over previous
#include <cuda_runtime.h>
#include <cuda_fp16.h>
#include <cuda_pipeline.h>
#include <cstdint>

#define NN   100000
#define NE   1600000
#define DD   128
#define NG   64
#define NCLS 16
#define SBS  512
#define SNB  ((NN + SBS - 1) / SBS)   // 196

// ---------------- device scratch (no allocs; zero-init on load) ----------------
__device__ __align__(16) __half d_hb[NN * DD];      // h in fp16
__device__ __align__(16) __half d_neighb[NN * DD];  // aggregated (fp16)
__device__ __align__(16) __half d_x1b[NN * DD];
__device__ __align__(16) __half d_wimg[2][128 * 256]; // [layer][n][k0..255]
__device__ float d_gsum[NG * DD];
__device__ int d_deg[NN];
__device__ int d_off[NN];
__device__ int d_cursor[NN];
__device__ int d_sorted[NE];
__device__ int d_gcnt[NG];
__device__ int d_total;

// ---------------- PTX helpers ----------------
__device__ __forceinline__ uint32_t smem_to_u32(const void* p) {
    uint32_t a;
    asm("{ .reg .u64 t; cvta.to.shared.u64 t, %1; cvt.u32.u64 %0, t; }" : "=r"(a) : "l"(p));
    return a;
}
__device__ __forceinline__ void ldsm4(uint32_t* r, uint32_t addr) {
    asm volatile("ldmatrix.sync.aligned.m8n8.x4.shared.b16 {%0,%1,%2,%3}, [%4];"
                 : "=r"(r[0]), "=r"(r[1]), "=r"(r[2]), "=r"(r[3]) : "r"(addr));
}
__device__ __forceinline__ void mma_f16(float* c, const uint32_t* a, const uint32_t* b) {
    asm volatile(
        "mma.sync.aligned.m16n8k16.row.col.f32.f16.f16.f32 "
        "{%0,%1,%2,%3},{%4,%5,%6,%7},{%8,%9},{%0,%1,%2,%3};"
        : "+f"(c[0]), "+f"(c[1]), "+f"(c[2]), "+f"(c[3])
        : "r"(a[0]), "r"(a[1]), "r"(a[2]), "r"(a[3]), "r"(b[0]), "r"(b[1]));
}

// ---- #1: h fp32->fp16 + degree/graph counting + weight images ----
__global__ void k_cvth_count(const float4* __restrict__ in, uint4* __restrict__ out,
                             const int* __restrict__ dst, const int* __restrict__ gid,
                             const float* __restrict__ W1s, const float* __restrict__ W1n,
                             const float* __restrict__ W2s, const float* __restrict__ W2n) {
    int i = blockIdx.x * blockDim.x + threadIdx.x;   // covers 1.6M
    if (i < NE) atomicAdd(&d_deg[dst[i]], 1);
    if (i < NN) atomicAdd(&d_gcnt[gid[i]], 1);
    if (i < 2 * 128 * 128) {                          // weight images (both layers)
        int layer = i >> 14;
        int j = i & 16383;
        int k = j >> 7, n = j & 127;
        const float* Ws = layer ? W2s : W1s;
        const float* Wn = layer ? W2n : W1n;
        d_wimg[layer][n * 256 + k]       = __float2half_rn(Ws[k * 128 + n]);
        d_wimg[layer][n * 256 + 128 + k] = __float2half_rn(Wn[k * 128 + n]);
    }
    if (i >= NN * DD / 8) return;
    float4 a = in[2 * i], b = in[2 * i + 1];
    __half2 p0 = __floats2half2_rn(a.x, a.y);
    __half2 p1 = __floats2half2_rn(a.z, a.w);
    __half2 p2 = __floats2half2_rn(b.x, b.y);
    __half2 p3 = __floats2half2_rn(b.z, b.w);
    uint4 o;
    o.x = *(uint32_t*)&p0; o.y = *(uint32_t*)&p1;
    o.z = *(uint32_t*)&p2; o.w = *(uint32_t*)&p3;
    out[i] = o;
}

// ---- #2: single-pass scan via atomic ticket (ranges disjoint, order-free) ----
__global__ void k_scan_atomic() {
    __shared__ int wsum[16];
    __shared__ int sbase;
    int t = threadIdx.x, lane = t & 31, w = t >> 5;
    int i = blockIdx.x * SBS + t;
    int v = (i < NN) ? d_deg[i] : 0;
    int x = v;
#pragma unroll
    for (int s = 1; s < 32; s <<= 1) {
        int y = __shfl_up_sync(0xFFFFFFFFu, x, s);
        if (lane >= s) x += y;
    }
    if (lane == 31) wsum[w] = x;
    __syncthreads();
    if (w == 0) {
        int ws = (lane < 16) ? wsum[lane] : 0;
#pragma unroll
        for (int s = 1; s < 16; s <<= 1) {
            int y = __shfl_up_sync(0xFFFFFFFFu, ws, s);
            if (lane >= s) ws += y;
        }
        if (lane < 16) wsum[lane] = ws;
    }
    __syncthreads();
    int incl = x + ((w > 0) ? wsum[w - 1] : 0);
    if (t == SBS - 1) sbase = atomicAdd(&d_total, incl);
    __syncthreads();
    if (i < NN) {
        int off = sbase + incl - v;
        d_off[i] = off;
        d_cursor[i] = off;
    }
}

// ---- #3: scatter edges into per-dst ranges ----
__global__ void k_scatter(const int* __restrict__ src, const int* __restrict__ dst) {
    int e = blockIdx.x * blockDim.x + threadIdx.x;
    if (e < NE) {
        int p = atomicAdd(&d_cursor[dst[e]], 1);
        d_sorted[p] = src[e];
    }
}

// ---- #4 / #6: aggregation (2 edges/iter, fp16 accumulate) ----
__global__ void k_agg(const uint4* __restrict__ feat) {
    int warp = (blockIdx.x * blockDim.x + threadIdx.x) >> 5;
    int lane = threadIdx.x & 31;
    if (warp >= NN) return;
    const int half = lane >> 4;      // which edge of the pair
    const int sub = lane & 15;       // uint4 index within 256B row
    int e0 = d_off[warp];
    int deg = d_deg[warp];
    int e1 = e0 + deg;

    __half2 a0 = __float2half2_rn(0.f), a1 = a0, a2 = a0, a3 = a0;
    int e = e0;
#pragma unroll 4
    for (; e + 1 < e1; e += 2) {
        int s = __ldg(&d_sorted[e + half]);
        uint4 v = __ldg(&feat[s * 16 + sub]);
        a0 = __hadd2(a0, *(__half2*)&v.x);
        a1 = __hadd2(a1, *(__half2*)&v.y);
        a2 = __hadd2(a2, *(__half2*)&v.z);
        a3 = __hadd2(a3, *(__half2*)&v.w);
    }
    if (e < e1 && half == 0) {       // odd remainder: lanes 0-15 only
        int s = __ldg(&d_sorted[e]);
        uint4 v = __ldg(&feat[s * 16 + sub]);
        a0 = __hadd2(a0, *(__half2*)&v.x);
        a1 = __hadd2(a1, *(__half2*)&v.y);
        a2 = __hadd2(a2, *(__half2*)&v.z);
        a3 = __hadd2(a3, *(__half2*)&v.w);
    }

    // merge the two halves in fp32, scale by 1/deg, pack, write by lanes 0-15
    float2 f0 = __half22float2(a0), f1 = __half22float2(a1);
    float2 f2 = __half22float2(a2), f3 = __half22float2(a3);
    float fs[8] = { f0.x, f0.y, f1.x, f1.y, f2.x, f2.y, f3.x, f3.y };
    float inv = 1.0f / fmaxf((float)deg, 1.0f);
#pragma unroll
    for (int j = 0; j < 8; j++) {
        fs[j] += __shfl_xor_sync(0xFFFFFFFFu, fs[j], 16);
        fs[j] *= inv;
    }
    if (half == 0) {
        __half2 q0 = __floats2half2_rn(fs[0], fs[1]);
        __half2 q1 = __floats2half2_rn(fs[2], fs[3]);
        __half2 q2 = __floats2half2_rn(fs[4], fs[5]);
        __half2 q3 = __floats2half2_rn(fs[6], fs[7]);
        uint4 o;
        o.x = *(uint32_t*)&q0; o.y = *(uint32_t*)&q1;
        o.z = *(uint32_t*)&q2; o.w = *(uint32_t*)&q3;
        ((uint4*)d_neighb)[warp * 16 + sub] = o;
    }
}

// ---- #5 / #7: fused dual GEMM v3 — 128m x 64n, K-split A staging, 3 CTAs/SM ----
// D[128m,64n] = [As|An](128x256) @ Bimg_half(64n x 256k)^T
// A staged in two K=128 halves (self, then neigh) into one 34.8KB buffer.
#define AROW 272                          // A row stride: 128 halves + 16B pad
#define BROW 528                          // B row stride: 256 halves + 16B pad
#define SMA  (128 * AROW)                 // 34816
#define SMB  (64 * BROW)                  // 33792
#define SM_TOT (SMA + SMB)                // 68608 -> 3 CTAs/SM

__global__ void __launch_bounds__(256, 3) k_gemm_mma(
    const uint4* __restrict__ Aself, const uint4* __restrict__ Aneigh,
    const uint4* __restrict__ Bimg, const float* __restrict__ bias,
    uint32_t* __restrict__ outp, const int* __restrict__ gid, int mode)
    // mode 0: relu + store fp16; mode 1: no relu, pool into d_gsum (no store)
{
    extern __shared__ __align__(16) char smem[];
    char* sA = smem;
    char* sB = smem + SMA;
    const int tid = threadIdx.x;
    const int wid = tid >> 5;
    const int lane = tid & 31;
    const int m_base = (blockIdx.x >> 1) * 128;
    const int n_base = (blockIdx.x & 1) * 64;

    // stage B (full K=256) + A-self (K=0..127) via cp.async
#pragma unroll
    for (int it = 0; it < 8; it++) {
        int idx = it * 256 + tid;           // 0..2047
        int row = idx >> 5, q = idx & 31;
        __pipeline_memcpy_async(sB + row * BROW + q * 16,
                                &Bimg[(n_base + row) * 32 + q], 16, 0);
    }
#pragma unroll
    for (int it = 0; it < 8; it++) {
        int idx = it * 256 + tid;           // 0..2047
        int row = idx >> 4, q = idx & 15;   // 128 rows x 16 uint4
        int m = m_base + row;
        __pipeline_memcpy_async(sA + row * AROW + q * 16,
                                &Aself[m * 16 + q], 16, (m < NN) ? 0 : 16);
    }
    __pipeline_commit();
    __pipeline_wait_prior(0);
    __syncthreads();

    const int warpM = wid >> 1;   // 0..3 -> 32-row band
    const int warpN = wid & 1;    // 0..1 -> 32-col band

    float acc[2][4][4];
#pragma unroll
    for (int i = 0; i < 2; i++)
#pragma unroll
        for (int j = 0; j < 4; j++)
#pragma unroll
            for (int p = 0; p < 4; p++) acc[i][j][p] = 0.f;

    uint32_t aBase = smem_to_u32(sA) + (warpM * 32 + (lane & 15)) * AROW + (lane >> 4) * 16;
    uint32_t bBase = smem_to_u32(sB) +
                     (warpN * 32 + (lane & 7) + ((lane >> 4) & 1) * 8) * BROW +
                     ((lane >> 3) & 1) * 16;

#pragma unroll 1
    for (int phase = 0; phase < 2; phase++) {
        if (phase == 1) {
            __syncthreads();   // all ldsm reads of A-self done
#pragma unroll
            for (int it = 0; it < 8; it++) {
                int idx = it * 256 + tid;
                int row = idx >> 4, q = idx & 15;
                int m = m_base + row;
                __pipeline_memcpy_async(sA + row * AROW + q * 16,
                                        &Aneigh[m * 16 + q], 16, (m < NN) ? 0 : 16);
            }
            __pipeline_commit();
            __pipeline_wait_prior(0);
            __syncthreads();
        }
#pragma unroll
        for (int ks8 = 0; ks8 < 8; ks8++) {
            int ks = phase * 8 + ks8;
            uint32_t a[2][4];
            ldsm4(a[0], aBase + ks8 * 32);
            ldsm4(a[1], aBase + 16 * AROW + ks8 * 32);
            uint32_t b[2][4];
#pragma unroll
            for (int nb = 0; nb < 2; nb++)
                ldsm4(b[nb], bBase + nb * 16 * BROW + ks * 32);
#pragma unroll
            for (int mi = 0; mi < 2; mi++)
#pragma unroll
                for (int nb = 0; nb < 2; nb++) {
                    mma_f16(acc[mi][2 * nb],     a[mi], &b[nb][0]);
                    mma_f16(acc[mi][2 * nb + 1], a[mi], &b[nb][2]);
                }
        }
    }

    const int qcol = 2 * (lane & 3);
    const int qrow = lane >> 2;

    if (mode == 0) {
        // epilogue: bias + relu, fp16 pairs to global
#pragma unroll
        for (int ni = 0; ni < 4; ni++) {
            int n = n_base + warpN * 32 + ni * 8 + qcol;
            float b0 = bias[n], b1 = bias[n + 1];
#pragma unroll
            for (int mi = 0; mi < 2; mi++) {
                int m0 = m_base + warpM * 32 + mi * 16 + qrow;
#pragma unroll
                for (int half = 0; half < 2; half++) {
                    int m = m0 + half * 8;
                    if (m >= NN) continue;
                    float f0 = fmaxf(acc[mi][ni][2 * half]     + b0, 0.f);
                    float f1 = fmaxf(acc[mi][ni][2 * half + 1] + b1, 0.f);
                    __half2 pk = __floats2half2_rn(f0, f1);
                    outp[m * 64 + n / 2] = *(uint32_t*)&pk;
                }
            }
        }
    } else {
        // epilogue: bias (no relu), per-graph segmented pooling into d_gsum
        __syncthreads();                      // all ldsm reads done
        float* scr = (float*)sA;              // 128 x 65 fp32 = 33280 B (fits 34816)
        int* sg = (int*)(smem + SMA);         // gids, in sB region (done with B)
        if (tid < 128) {
            int m = m_base + tid;
            sg[tid] = (m < NN) ? gid[m] : -1;
        }
#pragma unroll
        for (int ni = 0; ni < 4; ni++) {
            int nl = warpN * 32 + ni * 8 + qcol;
            int n = n_base + nl;
            float b0 = bias[n], b1 = bias[n + 1];
#pragma unroll
            for (int mi = 0; mi < 2; mi++) {
                int ml0 = warpM * 32 + mi * 16 + qrow;
#pragma unroll
                for (int half = 0; half < 2; half++) {
                    int ml = ml0 + half * 8;
                    scr[ml * 65 + nl]     = acc[mi][ni][2 * half]     + b0;
                    scr[ml * 65 + nl + 1] = acc[mi][ni][2 * half + 1] + b1;
                }
            }
        }
        __syncthreads();
        if (tid < 64) {
            float pacc = 0.f;
            int cur = sg[0];
            for (int r = 0; r < 128; r++) {
                int m = m_base + r;
                if (m >= NN) break;
                int g = sg[r];
                if (g != cur) {
                    atomicAdd(&d_gsum[cur * DD + n_base + tid], pacc);
                    pacc = 0.f;
                    cur = g;
                }
                pacc += scr[r * 65 + tid];
            }
            if (cur >= 0) atomicAdd(&d_gsum[cur * DD + n_base + tid], pacc);
        }
    }
}

// ---- #8: classifier + cleanup ----
__global__ void k_cls_cleanup(const float* __restrict__ Wc, const float* __restrict__ bc,
                              float* __restrict__ out) {
    __shared__ float sm[DD];
    int b = blockIdx.x;
    int t = threadIdx.x;   // 256 threads
    if (b < NG) {
        if (t < DD) {
            float cnt = fmaxf((float)d_gcnt[b], 1.0f);
            sm[t] = d_gsum[b * DD + t] / cnt;
        }
        __syncthreads();
        if (t < NCLS) {
            float o = bc[t];
#pragma unroll 4
            for (int k = 0; k < DD; k++) o += sm[k] * Wc[k * NCLS + t];
            out[b * NCLS + t] = o;
        }
        if (t < DD) d_gsum[b * DD + t] = 0.f;
        if (t == 0) d_gcnt[b] = 0;
    }
    int i = b * 256 + t;
    if (i < NN) d_deg[i] = 0;
    if (i == 0) d_total = 0;
}

// ---------------- launch ----------------
extern "C" void kernel_launch(void* const* d_in, const int* in_sizes, int n_in,
                              void* d_out, int out_size)
{
    const float* h   = (const float*)d_in[0];
    const int*   src = (const int*)d_in[1];
    const int*   dst = (const int*)d_in[2];
    const int*   gid = (const int*)d_in[3];
    int wb = (in_sizes[4] == 1) ? 5 : 4;
    const float* W1s = (const float*)d_in[wb + 0];
    const float* W1n = (const float*)d_in[wb + 1];
    const float* b1  = (const float*)d_in[wb + 2];
    const float* W2s = (const float*)d_in[wb + 3];
    const float* W2n = (const float*)d_in[wb + 4];
    const float* b2  = (const float*)d_in[wb + 5];
    const float* Wc  = (const float*)d_in[wb + 6];
    const float* bc  = (const float*)d_in[wb + 7];
    float* out = (float*)d_out;

    void *phb, *pnb, *px1, *pw;
    cudaGetSymbolAddress(&phb, d_hb);
    cudaGetSymbolAddress(&pnb, d_neighb);
    cudaGetSymbolAddress(&px1, d_x1b);
    cudaGetSymbolAddress(&pw, d_wimg);
    __half* hb = (__half*)phb;
    __half* nb = (__half*)pnb;
    __half* x1 = (__half*)px1;
    const uint4* wimg = (const uint4*)pw;

    cudaFuncSetAttribute(k_gemm_mma, cudaFuncAttributeMaxDynamicSharedMemorySize, SM_TOT);

    const int GB = 2 * ((NN + 127) / 128);   // 1564 CTAs (128m x 64n tiles)
    const uint4* B1 = wimg;                  // each image = 4096 uint4
    const uint4* B2 = wimg + 4096;

    // #1: h conversion + counting + weight images
    k_cvth_count<<<(NN * DD / 8 + 255) / 256, 256>>>((const float4*)h, (uint4*)hb,
                                                     dst, gid, W1s, W1n, W2s, W2n);
    // #2: one-shot scan (atomic ticket)
    k_scan_atomic<<<SNB, SBS>>>();
    // #3: scatter
    k_scatter<<<(NE + 255) / 256, 256>>>(src, dst);
    // #4: layer-1 aggregation  <-- ncu capture slot
    k_agg<<<NN / 8, 256>>>((const uint4*)hb);
    // #5: layer-1 GEMM (relu, store x1)
    k_gemm_mma<<<GB, 256, SM_TOT>>>((const uint4*)hb, (const uint4*)nb, B1, b1,
                                    (uint32_t*)x1, gid, 0);
    // #6: layer-2 aggregation
    k_agg<<<NN / 8, 256>>>((const uint4*)x1);
    // #7: layer-2 GEMM + fused graph pooling into d_gsum
    k_gemm_mma<<<GB, 256, SM_TOT>>>((const uint4*)x1, (const uint4*)nb, B2, b2,
                                    (uint32_t*)x1, gid, 1);
    // #8: classifier + zero-invariant restore
    k_cls_cleanup<<<(NN + 255) / 256, 256>>>(Wc, bc, out);
}

// round 15
// speedup vs baseline: 1.0719x; 1.0096x over previous
#include <cuda_runtime.h>
#include <cuda_fp16.h>
#include <cuda_pipeline.h>
#include <cstdint>

#define NN   100000
#define NE   1600000
#define DD   128
#define NG   64
#define NCLS 16
#define SBS  512
#define SNB  ((NN + SBS - 1) / SBS)   // 196

// ---------------- device scratch (no allocs; zero-init on load) ----------------
__device__ __align__(16) __half d_hb[NN * DD];      // h in fp16
__device__ __align__(16) __half d_neighb[NN * DD];  // aggregated (fp16)
__device__ __align__(16) __half d_x1b[NN * DD];
__device__ __align__(16) __half d_wimg[2][128 * 256]; // [layer][n][k0..255]
__device__ float d_gsum[NG * DD];
__device__ int d_deg[NN];
__device__ int d_off[NN];
__device__ int d_cursor[NN];
__device__ int d_sorted[NE];
__device__ int d_gcnt[NG];
__device__ int d_total;

// ---------------- PTX helpers ----------------
__device__ __forceinline__ uint32_t smem_to_u32(const void* p) {
    uint32_t a;
    asm("{ .reg .u64 t; cvta.to.shared.u64 t, %1; cvt.u32.u64 %0, t; }" : "=r"(a) : "l"(p));
    return a;
}
__device__ __forceinline__ void ldsm4(uint32_t* r, uint32_t addr) {
    asm volatile("ldmatrix.sync.aligned.m8n8.x4.shared.b16 {%0,%1,%2,%3}, [%4];"
                 : "=r"(r[0]), "=r"(r[1]), "=r"(r[2]), "=r"(r[3]) : "r"(addr));
}
__device__ __forceinline__ void mma_f16(float* c, const uint32_t* a, const uint32_t* b) {
    asm volatile(
        "mma.sync.aligned.m16n8k16.row.col.f32.f16.f16.f32 "
        "{%0,%1,%2,%3},{%4,%5,%6,%7},{%8,%9},{%0,%1,%2,%3};"
        : "+f"(c[0]), "+f"(c[1]), "+f"(c[2]), "+f"(c[3])
        : "r"(a[0]), "r"(a[1]), "r"(a[2]), "r"(a[3]), "r"(b[0]), "r"(b[1]));
}

// ---- #1: h fp32->fp16 + degree/graph counting + weight images ----
__global__ void k_cvth_count(const float4* __restrict__ in, uint4* __restrict__ out,
                             const int* __restrict__ dst, const int* __restrict__ gid,
                             const float* __restrict__ W1s, const float* __restrict__ W1n,
                             const float* __restrict__ W2s, const float* __restrict__ W2n) {
    int i = blockIdx.x * blockDim.x + threadIdx.x;   // covers 1.6M
    if (i < NE) atomicAdd(&d_deg[dst[i]], 1);
    if (i < NN) atomicAdd(&d_gcnt[gid[i]], 1);
    if (i < 2 * 128 * 128) {                          // weight images (both layers)
        int layer = i >> 14;
        int j = i & 16383;
        int k = j >> 7, n = j & 127;
        const float* Ws = layer ? W2s : W1s;
        const float* Wn = layer ? W2n : W1n;
        d_wimg[layer][n * 256 + k]       = __float2half_rn(Ws[k * 128 + n]);
        d_wimg[layer][n * 256 + 128 + k] = __float2half_rn(Wn[k * 128 + n]);
    }
    if (i >= NN * DD / 8) return;
    float4 a = in[2 * i], b = in[2 * i + 1];
    __half2 p0 = __floats2half2_rn(a.x, a.y);
    __half2 p1 = __floats2half2_rn(a.z, a.w);
    __half2 p2 = __floats2half2_rn(b.x, b.y);
    __half2 p3 = __floats2half2_rn(b.z, b.w);
    uint4 o;
    o.x = *(uint32_t*)&p0; o.y = *(uint32_t*)&p1;
    o.z = *(uint32_t*)&p2; o.w = *(uint32_t*)&p3;
    out[i] = o;
}

// ---- #2: single-pass scan via atomic ticket (ranges disjoint, order-free) ----
__global__ void k_scan_atomic() {
    __shared__ int wsum[16];
    __shared__ int sbase;
    int t = threadIdx.x, lane = t & 31, w = t >> 5;
    int i = blockIdx.x * SBS + t;
    int v = (i < NN) ? d_deg[i] : 0;
    int x = v;
#pragma unroll
    for (int s = 1; s < 32; s <<= 1) {
        int y = __shfl_up_sync(0xFFFFFFFFu, x, s);
        if (lane >= s) x += y;
    }
    if (lane == 31) wsum[w] = x;
    __syncthreads();
    if (w == 0) {
        int ws = (lane < 16) ? wsum[lane] : 0;
#pragma unroll
        for (int s = 1; s < 16; s <<= 1) {
            int y = __shfl_up_sync(0xFFFFFFFFu, ws, s);
            if (lane >= s) ws += y;
        }
        if (lane < 16) wsum[lane] = ws;
    }
    __syncthreads();
    int incl = x + ((w > 0) ? wsum[w - 1] : 0);
    if (t == SBS - 1) sbase = atomicAdd(&d_total, incl);
    __syncthreads();
    if (i < NN) {
        int off = sbase + incl - v;
        d_off[i] = off;
        d_cursor[i] = off;
    }
}

// ---- #3: scatter edges into per-dst ranges ----
__global__ void k_scatter(const int* __restrict__ src, const int* __restrict__ dst) {
    int e = blockIdx.x * blockDim.x + threadIdx.x;
    if (e < NE) {
        int p = atomicAdd(&d_cursor[dst[e]], 1);
        d_sorted[p] = src[e];
    }
}

// ---- #4 / #6: aggregation (2 edges/iter, unroll 8, fp16 accumulate) ----
__global__ void k_agg(const uint4* __restrict__ feat) {
    int warp = (blockIdx.x * blockDim.x + threadIdx.x) >> 5;
    int lane = threadIdx.x & 31;
    if (warp >= NN) return;
    const int half = lane >> 4;      // which edge of the pair
    const int sub = lane & 15;       // uint4 index within 256B row
    int e0 = d_off[warp];
    int deg = d_deg[warp];
    int e1 = e0 + deg;

    __half2 a0 = __float2half2_rn(0.f), a1 = a0, a2 = a0, a3 = a0;
    int e = e0;
#pragma unroll 8
    for (; e + 1 < e1; e += 2) {
        int s = __ldg(&d_sorted[e + half]);
        uint4 v = __ldg(&feat[s * 16 + sub]);
        a0 = __hadd2(a0, *(__half2*)&v.x);
        a1 = __hadd2(a1, *(__half2*)&v.y);
        a2 = __hadd2(a2, *(__half2*)&v.z);
        a3 = __hadd2(a3, *(__half2*)&v.w);
    }
    if (e < e1 && half == 0) {       // odd remainder: lanes 0-15 only
        int s = __ldg(&d_sorted[e]);
        uint4 v = __ldg(&feat[s * 16 + sub]);
        a0 = __hadd2(a0, *(__half2*)&v.x);
        a1 = __hadd2(a1, *(__half2*)&v.y);
        a2 = __hadd2(a2, *(__half2*)&v.z);
        a3 = __hadd2(a3, *(__half2*)&v.w);
    }

    // merge the two halves in fp32, scale by 1/deg, pack, write by lanes 0-15
    float2 f0 = __half22float2(a0), f1 = __half22float2(a1);
    float2 f2 = __half22float2(a2), f3 = __half22float2(a3);
    float fs[8] = { f0.x, f0.y, f1.x, f1.y, f2.x, f2.y, f3.x, f3.y };
    float inv = 1.0f / fmaxf((float)deg, 1.0f);
#pragma unroll
    for (int j = 0; j < 8; j++) {
        fs[j] += __shfl_xor_sync(0xFFFFFFFFu, fs[j], 16);
        fs[j] *= inv;
    }
    if (half == 0) {
        __half2 q0 = __floats2half2_rn(fs[0], fs[1]);
        __half2 q1 = __floats2half2_rn(fs[2], fs[3]);
        __half2 q2 = __floats2half2_rn(fs[4], fs[5]);
        __half2 q3 = __floats2half2_rn(fs[6], fs[7]);
        uint4 o;
        o.x = *(uint32_t*)&q0; o.y = *(uint32_t*)&q1;
        o.z = *(uint32_t*)&q2; o.w = *(uint32_t*)&q3;
        ((uint4*)d_neighb)[warp * 16 + sub] = o;
    }
}

// ---- #5 / #7: fused dual GEMM v4 — K-split A AND B staging, 4 CTAs/SM ----
// D[128m,64n] = [As|An](128x256) @ Bimg_half(64n x 256k)^T
// Phase p: A = (p?neigh:self) K-half, B = K-half p. One 34.8KB A buf + 17.4KB B buf.
#define AROW 272                          // A row stride: 128 halves + 16B pad
#define BROW 272                          // B half row stride: 128 halves + 16B pad
#define SMA  (128 * AROW)                 // 34816
#define SMB  (64 * BROW)                  // 17408
#define SM_TOT (SMA + SMB)                // 52224 -> 4 CTAs/SM (smem); regs capped 64

__global__ void __launch_bounds__(256, 4) k_gemm_mma(
    const uint4* __restrict__ Aself, const uint4* __restrict__ Aneigh,
    const uint4* __restrict__ Bimg, const float* __restrict__ bias,
    uint32_t* __restrict__ outp, const int* __restrict__ gid, int mode)
    // mode 0: relu + store fp16; mode 1: no relu, pool into d_gsum (no store)
{
    extern __shared__ __align__(16) char smem[];
    char* sA = smem;
    char* sB = smem + SMA;
    const int tid = threadIdx.x;
    const int wid = tid >> 5;
    const int lane = tid & 31;
    const int m_base = (blockIdx.x >> 1) * 128;
    const int n_base = (blockIdx.x & 1) * 64;

    const int warpM = wid >> 1;   // 0..3 -> 32-row band
    const int warpN = wid & 1;    // 0..1 -> 32-col band

    float acc[2][4][4];
#pragma unroll
    for (int i = 0; i < 2; i++)
#pragma unroll
        for (int j = 0; j < 4; j++)
#pragma unroll
            for (int p = 0; p < 4; p++) acc[i][j][p] = 0.f;

    uint32_t aBase = smem_to_u32(sA) + (warpM * 32 + (lane & 15)) * AROW + (lane >> 4) * 16;
    uint32_t bBase = smem_to_u32(sB) +
                     (warpN * 32 + (lane & 7) + ((lane >> 4) & 1) * 8) * BROW +
                     ((lane >> 3) & 1) * 16;

#pragma unroll 1
    for (int phase = 0; phase < 2; phase++) {
        if (phase == 1) __syncthreads();   // all ldsm reads of phase 0 done
        const uint4* Asrc = phase ? Aneigh : Aself;
        // stage A K-half: 128 rows x 16 uint4
#pragma unroll
        for (int it = 0; it < 8; it++) {
            int idx = it * 256 + tid;
            int row = idx >> 4, q = idx & 15;
            int m = m_base + row;
            __pipeline_memcpy_async(sA + row * AROW + q * 16,
                                    &Asrc[m * 16 + q], 16, (m < NN) ? 0 : 16);
        }
        // stage B K-half: 64 rows x 16 uint4 (cols k = phase*128 .. +127)
#pragma unroll
        for (int it = 0; it < 4; it++) {
            int idx = it * 256 + tid;
            int row = idx >> 4, q = idx & 15;
            __pipeline_memcpy_async(sB + row * BROW + q * 16,
                                    &Bimg[(n_base + row) * 32 + phase * 16 + q], 16, 0);
        }
        __pipeline_commit();
        __pipeline_wait_prior(0);
        __syncthreads();

#pragma unroll
        for (int ks8 = 0; ks8 < 8; ks8++) {
            uint32_t a[2][4];
            ldsm4(a[0], aBase + ks8 * 32);
            ldsm4(a[1], aBase + 16 * AROW + ks8 * 32);
            uint32_t b[2][4];
#pragma unroll
            for (int nb = 0; nb < 2; nb++)
                ldsm4(b[nb], bBase + nb * 16 * BROW + ks8 * 32);
#pragma unroll
            for (int mi = 0; mi < 2; mi++)
#pragma unroll
                for (int nb = 0; nb < 2; nb++) {
                    mma_f16(acc[mi][2 * nb],     a[mi], &b[nb][0]);
                    mma_f16(acc[mi][2 * nb + 1], a[mi], &b[nb][2]);
                }
        }
    }

    const int qcol = 2 * (lane & 3);
    const int qrow = lane >> 2;

    if (mode == 0) {
        // epilogue: bias + relu, fp16 pairs to global
#pragma unroll
        for (int ni = 0; ni < 4; ni++) {
            int n = n_base + warpN * 32 + ni * 8 + qcol;
            float b0 = bias[n], b1 = bias[n + 1];
#pragma unroll
            for (int mi = 0; mi < 2; mi++) {
                int m0 = m_base + warpM * 32 + mi * 16 + qrow;
#pragma unroll
                for (int half = 0; half < 2; half++) {
                    int m = m0 + half * 8;
                    if (m >= NN) continue;
                    float f0 = fmaxf(acc[mi][ni][2 * half]     + b0, 0.f);
                    float f1 = fmaxf(acc[mi][ni][2 * half + 1] + b1, 0.f);
                    __half2 pk = __floats2half2_rn(f0, f1);
                    outp[m * 64 + n / 2] = *(uint32_t*)&pk;
                }
            }
        }
    } else {
        // epilogue: bias (no relu), per-graph segmented pooling into d_gsum
        __syncthreads();                      // all ldsm reads done
        float* scr = (float*)sA;              // 128 x 65 fp32 = 33280 B (fits 34816)
        int* sg = (int*)(smem + SMA);         // gids, in sB region (done with B)
        if (tid < 128) {
            int m = m_base + tid;
            sg[tid] = (m < NN) ? gid[m] : -1;
        }
#pragma unroll
        for (int ni = 0; ni < 4; ni++) {
            int nl = warpN * 32 + ni * 8 + qcol;
            int n = n_base + nl;
            float b0 = bias[n], b1 = bias[n + 1];
#pragma unroll
            for (int mi = 0; mi < 2; mi++) {
                int ml0 = warpM * 32 + mi * 16 + qrow;
#pragma unroll
                for (int half = 0; half < 2; half++) {
                    int ml = ml0 + half * 8;
                    scr[ml * 65 + nl]     = acc[mi][ni][2 * half]     + b0;
                    scr[ml * 65 + nl + 1] = acc[mi][ni][2 * half + 1] + b1;
                }
            }
        }
        __syncthreads();
        if (tid < 64) {
            float pacc = 0.f;
            int cur = sg[0];
            for (int r = 0; r < 128; r++) {
                int m = m_base + r;
                if (m >= NN) break;
                int g = sg[r];
                if (g != cur) {
                    atomicAdd(&d_gsum[cur * DD + n_base + tid], pacc);
                    pacc = 0.f;
                    cur = g;
                }
                pacc += scr[r * 65 + tid];
            }
            if (cur >= 0) atomicAdd(&d_gsum[cur * DD + n_base + tid], pacc);
        }
    }
}

// ---- #8: classifier + cleanup ----
__global__ void k_cls_cleanup(const float* __restrict__ Wc, const float* __restrict__ bc,
                              float* __restrict__ out) {
    __shared__ float sm[DD];
    int b = blockIdx.x;
    int t = threadIdx.x;   // 256 threads
    if (b < NG) {
        if (t < DD) {
            float cnt = fmaxf((float)d_gcnt[b], 1.0f);
            sm[t] = d_gsum[b * DD + t] / cnt;
        }
        __syncthreads();
        if (t < NCLS) {
            float o = bc[t];
#pragma unroll 4
            for (int k = 0; k < DD; k++) o += sm[k] * Wc[k * NCLS + t];
            out[b * NCLS + t] = o;
        }
        if (t < DD) d_gsum[b * DD + t] = 0.f;
        if (t == 0) d_gcnt[b] = 0;
    }
    int i = b * 256 + t;
    if (i < NN) d_deg[i] = 0;
    if (i == 0) d_total = 0;
}

// ---------------- launch ----------------
extern "C" void kernel_launch(void* const* d_in, const int* in_sizes, int n_in,
                              void* d_out, int out_size)
{
    const float* h   = (const float*)d_in[0];
    const int*   src = (const int*)d_in[1];
    const int*   dst = (const int*)d_in[2];
    const int*   gid = (const int*)d_in[3];
    int wb = (in_sizes[4] == 1) ? 5 : 4;
    const float* W1s = (const float*)d_in[wb + 0];
    const float* W1n = (const float*)d_in[wb + 1];
    const float* b1  = (const float*)d_in[wb + 2];
    const float* W2s = (const float*)d_in[wb + 3];
    const float* W2n = (const float*)d_in[wb + 4];
    const float* b2  = (const float*)d_in[wb + 5];
    const float* Wc  = (const float*)d_in[wb + 6];
    const float* bc  = (const float*)d_in[wb + 7];
    float* out = (float*)d_out;

    void *phb, *pnb, *px1, *pw;
    cudaGetSymbolAddress(&phb, d_hb);
    cudaGetSymbolAddress(&pnb, d_neighb);
    cudaGetSymbolAddress(&px1, d_x1b);
    cudaGetSymbolAddress(&pw, d_wimg);
    __half* hb = (__half*)phb;
    __half* nb = (__half*)pnb;
    __half* x1 = (__half*)px1;
    const uint4* wimg = (const uint4*)pw;

    cudaFuncSetAttribute(k_gemm_mma, cudaFuncAttributeMaxDynamicSharedMemorySize, SM_TOT);

    const int GB = 2 * ((NN + 127) / 128);   // 1564 CTAs (128m x 64n tiles)
    const uint4* B1 = wimg;                  // each image = 4096 uint4
    const uint4* B2 = wimg + 4096;

    // #1: h conversion + counting + weight images
    k_cvth_count<<<(NN * DD / 8 + 255) / 256, 256>>>((const float4*)h, (uint4*)hb,
                                                     dst, gid, W1s, W1n, W2s, W2n);
    // #2: one-shot scan (atomic ticket)
    k_scan_atomic<<<SNB, SBS>>>();
    // #3: scatter
    k_scatter<<<(NE + 255) / 256, 256>>>(src, dst);
    // #4: layer-1 aggregation  <-- ncu capture slot
    k_agg<<<NN / 8, 256>>>((const uint4*)hb);
    // #5: layer-1 GEMM (relu, store x1)
    k_gemm_mma<<<GB, 256, SM_TOT>>>((const uint4*)hb, (const uint4*)nb, B1, b1,
                                    (uint32_t*)x1, gid, 0);
    // #6: layer-2 aggregation
    k_agg<<<NN / 8, 256>>>((const uint4*)x1);
    // #7: layer-2 GEMM + fused graph pooling into d_gsum
    k_gemm_mma<<<GB, 256, SM_TOT>>>((const uint4*)x1, (const uint4*)nb, B2, b2,
                                    (uint32_t*)x1, gid, 1);
    // #8: classifier + zero-invariant restore
    k_cls_cleanup<<<(NN + 255) / 256, 256>>>(Wc, bc, out);
}

// round 16
// speedup vs baseline: 1.0793x; 1.0069x over previous
#include <cuda_runtime.h>
#include <cuda_fp16.h>
#include <cuda_pipeline.h>
#include <cstdint>

#define NN   100000
#define NE   1600000
#define DD   128
#define NG   64
#define NCLS 16
#define SBS  512
#define SNB  ((NN + SBS - 1) / SBS)   // 196

// ---------------- device scratch (no allocs; zero-init on load) ----------------
__device__ __align__(16) __half d_hb[NN * DD];      // h in fp16
__device__ __align__(16) __half d_neighb[NN * DD];  // aggregated (fp16)
__device__ __align__(16) __half d_x1b[NN * DD];
__device__ __align__(16) __half d_wimg[2][128 * 256]; // [layer][n][k0..255]
__device__ float d_gsum[NG * DD];
__device__ int d_deg[NN];
__device__ int d_off[NN];
__device__ int d_cursor[NN];
__device__ int d_sorted[NE];
__device__ int d_gcnt[NG];
__device__ int d_total;

// ---------------- PTX helpers ----------------
__device__ __forceinline__ uint32_t smem_to_u32(const void* p) {
    uint32_t a;
    asm("{ .reg .u64 t; cvta.to.shared.u64 t, %1; cvt.u32.u64 %0, t; }" : "=r"(a) : "l"(p));
    return a;
}
__device__ __forceinline__ void ldsm4(uint32_t* r, uint32_t addr) {
    asm volatile("ldmatrix.sync.aligned.m8n8.x4.shared.b16 {%0,%1,%2,%3}, [%4];"
                 : "=r"(r[0]), "=r"(r[1]), "=r"(r[2]), "=r"(r[3]) : "r"(addr));
}
__device__ __forceinline__ void mma_f16(float* c, const uint32_t* a, const uint32_t* b) {
    asm volatile(
        "mma.sync.aligned.m16n8k16.row.col.f32.f16.f16.f32 "
        "{%0,%1,%2,%3},{%4,%5,%6,%7},{%8,%9},{%0,%1,%2,%3};"
        : "+f"(c[0]), "+f"(c[1]), "+f"(c[2]), "+f"(c[3])
        : "r"(a[0]), "r"(a[1]), "r"(a[2]), "r"(a[3]), "r"(b[0]), "r"(b[1]));
}

// ---- #1: weight images (both layers) ----
__global__ void k_cvtw(const float* __restrict__ W1s, const float* __restrict__ W1n,
                       const float* __restrict__ W2s, const float* __restrict__ W2n) {
    int i = blockIdx.x * blockDim.x + threadIdx.x;   // 0..32767
    if (i >= 2 * 128 * 128) return;
    int layer = i >> 14;
    int j = i & 16383;
    int k = j >> 7, n = j & 127;
    const float* Ws = layer ? W2s : W1s;
    const float* Wn = layer ? W2n : W1n;
    d_wimg[layer][n * 256 + k]       = __float2half_rn(Ws[k * 128 + n]);
    d_wimg[layer][n * 256 + 128 + k] = __float2half_rn(Wn[k * 128 + n]);
}

// ---- #2: h fp32->fp16 + degree/graph counting ----
__global__ void k_cvth_count(const float4* __restrict__ in, uint4* __restrict__ out,
                             const int* __restrict__ dst, const int* __restrict__ gid) {
    int i = blockIdx.x * blockDim.x + threadIdx.x;   // covers 1.6M
    if (i < NE) atomicAdd(&d_deg[dst[i]], 1);
    if (i < NN) atomicAdd(&d_gcnt[gid[i]], 1);
    if (i >= NN * DD / 8) return;
    float4 a = in[2 * i], b = in[2 * i + 1];
    __half2 p0 = __floats2half2_rn(a.x, a.y);
    __half2 p1 = __floats2half2_rn(a.z, a.w);
    __half2 p2 = __floats2half2_rn(b.x, b.y);
    __half2 p3 = __floats2half2_rn(b.z, b.w);
    uint4 o;
    o.x = *(uint32_t*)&p0; o.y = *(uint32_t*)&p1;
    o.z = *(uint32_t*)&p2; o.w = *(uint32_t*)&p3;
    out[i] = o;
}

// ---- #3: single-pass scan via atomic ticket (ranges disjoint, order-free) ----
__global__ void k_scan_atomic() {
    __shared__ int wsum[16];
    __shared__ int sbase;
    int t = threadIdx.x, lane = t & 31, w = t >> 5;
    int i = blockIdx.x * SBS + t;
    int v = (i < NN) ? d_deg[i] : 0;
    int x = v;
#pragma unroll
    for (int s = 1; s < 32; s <<= 1) {
        int y = __shfl_up_sync(0xFFFFFFFFu, x, s);
        if (lane >= s) x += y;
    }
    if (lane == 31) wsum[w] = x;
    __syncthreads();
    if (w == 0) {
        int ws = (lane < 16) ? wsum[lane] : 0;
#pragma unroll
        for (int s = 1; s < 16; s <<= 1) {
            int y = __shfl_up_sync(0xFFFFFFFFu, ws, s);
            if (lane >= s) ws += y;
        }
        if (lane < 16) wsum[lane] = ws;
    }
    __syncthreads();
    int incl = x + ((w > 0) ? wsum[w - 1] : 0);
    if (t == SBS - 1) sbase = atomicAdd(&d_total, incl);
    __syncthreads();
    if (i < NN) {
        int off = sbase + incl - v;
        d_off[i] = off;
        d_cursor[i] = off;
    }
}

// ---- #4: scatter edges into per-dst ranges (PROFILED) ----
__global__ void k_scatter(const int* __restrict__ src, const int* __restrict__ dst) {
    int base = (blockIdx.x * blockDim.x + threadIdx.x) * 4;
#pragma unroll
    for (int j = 0; j < 4; j++) {
        int e = base + j;
        if (e < NE) {
            int p = atomicAdd(&d_cursor[dst[e]], 1);
            d_sorted[p] = src[e];
        }
    }
}

// ---- #5 / #7: aggregation (2 edges/iter, unroll 4, fp16 accumulate) ----
__global__ void k_agg(const uint4* __restrict__ feat) {
    int warp = (blockIdx.x * blockDim.x + threadIdx.x) >> 5;
    int lane = threadIdx.x & 31;
    if (warp >= NN) return;
    const int half = lane >> 4;      // which edge of the pair
    const int sub = lane & 15;       // uint4 index within 256B row
    int e0 = d_off[warp];
    int deg = d_deg[warp];
    int e1 = e0 + deg;

    __half2 a0 = __float2half2_rn(0.f), a1 = a0, a2 = a0, a3 = a0;
    int e = e0;
#pragma unroll 4
    for (; e + 1 < e1; e += 2) {
        int s = __ldg(&d_sorted[e + half]);
        uint4 v = __ldg(&feat[s * 16 + sub]);
        a0 = __hadd2(a0, *(__half2*)&v.x);
        a1 = __hadd2(a1, *(__half2*)&v.y);
        a2 = __hadd2(a2, *(__half2*)&v.z);
        a3 = __hadd2(a3, *(__half2*)&v.w);
    }
    if (e < e1 && half == 0) {       // odd remainder: lanes 0-15 only
        int s = __ldg(&d_sorted[e]);
        uint4 v = __ldg(&feat[s * 16 + sub]);
        a0 = __hadd2(a0, *(__half2*)&v.x);
        a1 = __hadd2(a1, *(__half2*)&v.y);
        a2 = __hadd2(a2, *(__half2*)&v.z);
        a3 = __hadd2(a3, *(__half2*)&v.w);
    }

    // merge the two halves in fp32, scale by 1/deg, pack, write by lanes 0-15
    float2 f0 = __half22float2(a0), f1 = __half22float2(a1);
    float2 f2 = __half22float2(a2), f3 = __half22float2(a3);
    float fs[8] = { f0.x, f0.y, f1.x, f1.y, f2.x, f2.y, f3.x, f3.y };
    float inv = 1.0f / fmaxf((float)deg, 1.0f);
#pragma unroll
    for (int j = 0; j < 8; j++) {
        fs[j] += __shfl_xor_sync(0xFFFFFFFFu, fs[j], 16);
        fs[j] *= inv;
    }
    if (half == 0) {
        __half2 q0 = __floats2half2_rn(fs[0], fs[1]);
        __half2 q1 = __floats2half2_rn(fs[2], fs[3]);
        __half2 q2 = __floats2half2_rn(fs[4], fs[5]);
        __half2 q3 = __floats2half2_rn(fs[6], fs[7]);
        uint4 o;
        o.x = *(uint32_t*)&q0; o.y = *(uint32_t*)&q1;
        o.z = *(uint32_t*)&q2; o.w = *(uint32_t*)&q3;
        ((uint4*)d_neighb)[warp * 16 + sub] = o;
    }
}

// ---- #6 / #8: fused dual GEMM v4 — K-split A AND B staging, 4 CTAs/SM ----
#define AROW 272                          // A row stride: 128 halves + 16B pad
#define BROW 272                          // B half row stride: 128 halves + 16B pad
#define SMA  (128 * AROW)                 // 34816
#define SMB  (64 * BROW)                  // 17408
#define SM_TOT (SMA + SMB)                // 52224 -> 4 CTAs/SM

__global__ void __launch_bounds__(256, 4) k_gemm_mma(
    const uint4* __restrict__ Aself, const uint4* __restrict__ Aneigh,
    const uint4* __restrict__ Bimg, const float* __restrict__ bias,
    uint32_t* __restrict__ outp, const int* __restrict__ gid, int mode)
    // mode 0: relu + store fp16; mode 1: no relu, pool into d_gsum (no store)
{
    extern __shared__ __align__(16) char smem[];
    char* sA = smem;
    char* sB = smem + SMA;
    const int tid = threadIdx.x;
    const int wid = tid >> 5;
    const int lane = tid & 31;
    const int m_base = (blockIdx.x >> 1) * 128;
    const int n_base = (blockIdx.x & 1) * 64;

    const int warpM = wid >> 1;   // 0..3 -> 32-row band
    const int warpN = wid & 1;    // 0..1 -> 32-col band

    float acc[2][4][4];
#pragma unroll
    for (int i = 0; i < 2; i++)
#pragma unroll
        for (int j = 0; j < 4; j++)
#pragma unroll
            for (int p = 0; p < 4; p++) acc[i][j][p] = 0.f;

    uint32_t aBase = smem_to_u32(sA) + (warpM * 32 + (lane & 15)) * AROW + (lane >> 4) * 16;
    uint32_t bBase = smem_to_u32(sB) +
                     (warpN * 32 + (lane & 7) + ((lane >> 4) & 1) * 8) * BROW +
                     ((lane >> 3) & 1) * 16;

#pragma unroll 1
    for (int phase = 0; phase < 2; phase++) {
        if (phase == 1) __syncthreads();   // all ldsm reads of phase 0 done
        const uint4* Asrc = phase ? Aneigh : Aself;
#pragma unroll
        for (int it = 0; it < 8; it++) {
            int idx = it * 256 + tid;
            int row = idx >> 4, q = idx & 15;
            int m = m_base + row;
            __pipeline_memcpy_async(sA + row * AROW + q * 16,
                                    &Asrc[m * 16 + q], 16, (m < NN) ? 0 : 16);
        }
#pragma unroll
        for (int it = 0; it < 4; it++) {
            int idx = it * 256 + tid;
            int row = idx >> 4, q = idx & 15;
            __pipeline_memcpy_async(sB + row * BROW + q * 16,
                                    &Bimg[(n_base + row) * 32 + phase * 16 + q], 16, 0);
        }
        __pipeline_commit();
        __pipeline_wait_prior(0);
        __syncthreads();

#pragma unroll
        for (int ks8 = 0; ks8 < 8; ks8++) {
            uint32_t a[2][4];
            ldsm4(a[0], aBase + ks8 * 32);
            ldsm4(a[1], aBase + 16 * AROW + ks8 * 32);
            uint32_t b[2][4];
#pragma unroll
            for (int nb = 0; nb < 2; nb++)
                ldsm4(b[nb], bBase + nb * 16 * BROW + ks8 * 32);
#pragma unroll
            for (int mi = 0; mi < 2; mi++)
#pragma unroll
                for (int nb = 0; nb < 2; nb++) {
                    mma_f16(acc[mi][2 * nb],     a[mi], &b[nb][0]);
                    mma_f16(acc[mi][2 * nb + 1], a[mi], &b[nb][2]);
                }
        }
    }

    const int qcol = 2 * (lane & 3);
    const int qrow = lane >> 2;

    if (mode == 0) {
#pragma unroll
        for (int ni = 0; ni < 4; ni++) {
            int n = n_base + warpN * 32 + ni * 8 + qcol;
            float b0 = bias[n], b1 = bias[n + 1];
#pragma unroll
            for (int mi = 0; mi < 2; mi++) {
                int m0 = m_base + warpM * 32 + mi * 16 + qrow;
#pragma unroll
                for (int half = 0; half < 2; half++) {
                    int m = m0 + half * 8;
                    if (m >= NN) continue;
                    float f0 = fmaxf(acc[mi][ni][2 * half]     + b0, 0.f);
                    float f1 = fmaxf(acc[mi][ni][2 * half + 1] + b1, 0.f);
                    __half2 pk = __floats2half2_rn(f0, f1);
                    outp[m * 64 + n / 2] = *(uint32_t*)&pk;
                }
            }
        }
    } else {
        // epilogue: bias (no relu), per-graph segmented pooling into d_gsum
        __syncthreads();                      // all ldsm reads done
        float* scr = (float*)sA;              // 128 x 65 fp32 = 33280 B (fits 34816)
        int* sg = (int*)(smem + SMA);         // gids, in sB region (done with B)
        if (tid < 128) {
            int m = m_base + tid;
            sg[tid] = (m < NN) ? gid[m] : -1;
        }
#pragma unroll
        for (int ni = 0; ni < 4; ni++) {
            int nl = warpN * 32 + ni * 8 + qcol;
            int n = n_base + nl;
            float b0 = bias[n], b1 = bias[n + 1];
#pragma unroll
            for (int mi = 0; mi < 2; mi++) {
                int ml0 = warpM * 32 + mi * 16 + qrow;
#pragma unroll
                for (int half = 0; half < 2; half++) {
                    int ml = ml0 + half * 8;
                    scr[ml * 65 + nl]     = acc[mi][ni][2 * half]     + b0;
                    scr[ml * 65 + nl + 1] = acc[mi][ni][2 * half + 1] + b1;
                }
            }
        }
        __syncthreads();
        if (tid < 64) {
            float pacc = 0.f;
            int cur = sg[0];
            for (int r = 0; r < 128; r++) {
                int m = m_base + r;
                if (m >= NN) break;
                int g = sg[r];
                if (g != cur) {
                    atomicAdd(&d_gsum[cur * DD + n_base + tid], pacc);
                    pacc = 0.f;
                    cur = g;
                }
                pacc += scr[r * 65 + tid];
            }
            if (cur >= 0) atomicAdd(&d_gsum[cur * DD + n_base + tid], pacc);
        }
    }
}

// ---- #9: classifier + cleanup ----
__global__ void k_cls_cleanup(const float* __restrict__ Wc, const float* __restrict__ bc,
                              float* __restrict__ out) {
    __shared__ float sm[DD];
    int b = blockIdx.x;
    int t = threadIdx.x;   // 256 threads
    if (b < NG) {
        if (t < DD) {
            float cnt = fmaxf((float)d_gcnt[b], 1.0f);
            sm[t] = d_gsum[b * DD + t] / cnt;
        }
        __syncthreads();
        if (t < NCLS) {
            float o = bc[t];
#pragma unroll 4
            for (int k = 0; k < DD; k++) o += sm[k] * Wc[k * NCLS + t];
            out[b * NCLS + t] = o;
        }
        if (t < DD) d_gsum[b * DD + t] = 0.f;
        if (t == 0) d_gcnt[b] = 0;
    }
    int i = b * 256 + t;
    if (i < NN) d_deg[i] = 0;
    if (i == 0) d_total = 0;
}

// ---------------- launch ----------------
extern "C" void kernel_launch(void* const* d_in, const int* in_sizes, int n_in,
                              void* d_out, int out_size)
{
    const float* h   = (const float*)d_in[0];
    const int*   src = (const int*)d_in[1];
    const int*   dst = (const int*)d_in[2];
    const int*   gid = (const int*)d_in[3];
    int wb = (in_sizes[4] == 1) ? 5 : 4;
    const float* W1s = (const float*)d_in[wb + 0];
    const float* W1n = (const float*)d_in[wb + 1];
    const float* b1  = (const float*)d_in[wb + 2];
    const float* W2s = (const float*)d_in[wb + 3];
    const float* W2n = (const float*)d_in[wb + 4];
    const float* b2  = (const float*)d_in[wb + 5];
    const float* Wc  = (const float*)d_in[wb + 6];
    const float* bc  = (const float*)d_in[wb + 7];
    float* out = (float*)d_out;

    void *phb, *pnb, *px1, *pw;
    cudaGetSymbolAddress(&phb, d_hb);
    cudaGetSymbolAddress(&pnb, d_neighb);
    cudaGetSymbolAddress(&px1, d_x1b);
    cudaGetSymbolAddress(&pw, d_wimg);
    __half* hb = (__half*)phb;
    __half* nb = (__half*)pnb;
    __half* x1 = (__half*)px1;
    const uint4* wimg = (const uint4*)pw;

    cudaFuncSetAttribute(k_gemm_mma, cudaFuncAttributeMaxDynamicSharedMemorySize, SM_TOT);

    const int GB = 2 * ((NN + 127) / 128);   // 1564 CTAs (128m x 64n tiles)
    const uint4* B1 = wimg;                  // each image = 4096 uint4
    const uint4* B2 = wimg + 4096;

    // #1: weight images
    k_cvtw<<<128, 256>>>(W1s, W1n, W2s, W2n);
    // #2: h conversion + degree/graph counting
    k_cvth_count<<<(NN * DD / 8 + 255) / 256, 256>>>((const float4*)h, (uint4*)hb, dst, gid);
    // #3: one-shot scan (atomic ticket)
    k_scan_atomic<<<SNB, SBS>>>();
    // #4: scatter  <-- ncu capture slot
    k_scatter<<<(NE / 4 + 255) / 256, 256>>>(src, dst);
    // #5: layer-1 aggregation
    k_agg<<<NN / 8, 256>>>((const uint4*)hb);
    // #6: layer-1 GEMM (relu, store x1)
    k_gemm_mma<<<GB, 256, SM_TOT>>>((const uint4*)hb, (const uint4*)nb, B1, b1,
                                    (uint32_t*)x1, gid, 0);
    // #7: layer-2 aggregation
    k_agg<<<NN / 8, 256>>>((const uint4*)x1);
    // #8: layer-2 GEMM + fused graph pooling into d_gsum
    k_gemm_mma<<<GB, 256, SM_TOT>>>((const uint4*)x1, (const uint4*)nb, B2, b2,
                                    (uint32_t*)x1, gid, 1);
    // #9: classifier + zero-invariant restore
    k_cls_cleanup<<<(NN + 255) / 256, 256>>>(Wc, bc, out);
}